// round 3
// baseline (speedup 1.0000x reference)
#include <cuda_runtime.h>
#include <math.h>

// ---------------------------------------------------------------------------
// STN, fp32 throughout (theta errors amplify x127 into pixel shifts).
// R1: packed fp32x2 FMA (FFMA2) in all conv kernels -> 2x fp32 pipe rate.
//     conv3 fuses the global-mean partial reduction (head no longer reads P3).
// ---------------------------------------------------------------------------

// Scratch (allocation-free contract: __device__ globals)
__device__ __align__(16) float g_P1[16 * 127 * 127 * 16];
__device__ __align__(16) float g_P2[16 * 62 * 62 * 32];
__device__ __align__(16) float g_part[16][16][32];   // [batch][tile][channel]
__device__ __align__(16) float g_theta[16 * 6];

// ---- packed f32x2 helpers (FFMA2: ptxas never emits; PTX-only) ------------
__device__ __forceinline__ unsigned long long pack2(float v) {
    unsigned long long r;
    asm("mov.b64 %0, {%1, %1};" : "=l"(r) : "r"(__float_as_uint(v)));
    return r;
}
__device__ __forceinline__ void ffma2(unsigned long long& a,
                                      unsigned long long v,
                                      unsigned long long w) {
    asm("fma.rn.f32x2 %0, %1, %2, %0;" : "+l"(a) : "l"(v), "l"(w));
}
__device__ __forceinline__ float2 unpack2(unsigned long long a) {
    float lo, hi;
    asm("mov.b64 {%0, %1}, %2;" : "=f"(lo), "=f"(hi) : "l"(a));
    return make_float2(lo, hi);
}

// 8 packed FMAs: one broadcast value vv against 16 consecutive couts (8 pairs)
__device__ __forceinline__ void fma8p(unsigned long long* a, unsigned long long vv,
                                      const ulonglong2& q0, const ulonglong2& q1,
                                      const ulonglong2& q2, const ulonglong2& q3) {
    ffma2(a[0], vv, q0.x); ffma2(a[1], vv, q0.y);
    ffma2(a[2], vv, q1.x); ffma2(a[3], vv, q1.y);
    ffma2(a[4], vv, q2.x); ffma2(a[5], vv, q2.y);
    ffma2(a[6], vv, q3.x); ffma2(a[7], vv, q3.y);
}

// ---------------------------------------------------------------------------
// conv1: x(16,256,256,32)*W1(3,3,32,16)+b1 -> relu -> pool2 -> P1(16,127,127,16)
// ---------------------------------------------------------------------------
__global__ __launch_bounds__(256, 2) void conv1_kernel(
    const float* __restrict__ x, const float* __restrict__ W,
    const float* __restrict__ bias)
{
    __shared__ __align__(16) float sW[3 * 3 * 32 * 16];  // [ky][kx][ci][co]
    __shared__ __align__(16) float sIn[4][34][35];       // [ci][row][col]

    const int b   = blockIdx.z;
    const int ph0 = blockIdx.y * 16, pw0 = blockIdx.x * 16;
    const int t   = threadIdx.x;
    const int py  = t >> 4, px = t & 15;

    for (int i = t; i < 4608; i += 256) sW[i] = W[i];

    unsigned long long acc[4][8];
#pragma unroll
    for (int k = 0; k < 4; ++k)
#pragma unroll
        for (int j = 0; j < 8; ++j) acc[k][j] = 0ULL;

    const int r0 = 2 * ph0, c0 = 2 * pw0;

    for (int cc = 0; cc < 8; ++cc) {
        __syncthreads();
        for (int i = t; i < 34 * 34; i += 256) {
            int r = i / 34, c = i - 34 * (i / 34);
            int gr = r0 + r, gc = c0 + c;
            float4 v = make_float4(0.f, 0.f, 0.f, 0.f);
            if (gr < 256 && gc < 256)
                v = *(const float4*)(x + (((size_t)(b * 256 + gr) * 256 + gc) * 32 + cc * 4));
            sIn[0][r][c] = v.x; sIn[1][r][c] = v.y;
            sIn[2][r][c] = v.z; sIn[3][r][c] = v.w;
        }
        __syncthreads();
#pragma unroll
        for (int ky = 0; ky < 3; ++ky)
#pragma unroll
            for (int kx = 0; kx < 3; ++kx)
#pragma unroll
                for (int ci = 0; ci < 4; ++ci) {
                    const ulonglong2* wp =
                        (const ulonglong2*)&sW[(((ky * 3 + kx) * 32) + (cc * 4 + ci)) * 16];
                    ulonglong2 q0 = wp[0], q1 = wp[1], q2 = wp[2], q3 = wp[3];
                    int rr = 2 * py + ky, cl = 2 * px + kx;
                    fma8p(acc[0], pack2(sIn[ci][rr][cl]),         q0, q1, q2, q3);
                    fma8p(acc[1], pack2(sIn[ci][rr][cl + 1]),     q0, q1, q2, q3);
                    fma8p(acc[2], pack2(sIn[ci][rr + 1][cl]),     q0, q1, q2, q3);
                    fma8p(acc[3], pack2(sIn[ci][rr + 1][cl + 1]), q0, q1, q2, q3);
                }
    }

    const int ph = ph0 + py, pw = pw0 + px;
    if (ph < 127 && pw < 127) {
        float* op = g_P1 + ((size_t)(b * 127 + ph) * 127 + pw) * 16;
#pragma unroll
        for (int j = 0; j < 8; ++j) {
            float2 a0 = unpack2(acc[0][j]), a1 = unpack2(acc[1][j]);
            float2 a2 = unpack2(acc[2][j]), a3 = unpack2(acc[3][j]);
            float mlo = fmaxf(fmaxf(a0.x, a1.x), fmaxf(a2.x, a3.x));
            float mhi = fmaxf(fmaxf(a0.y, a1.y), fmaxf(a2.y, a3.y));
            op[2 * j]     = fmaxf(mlo + bias[2 * j], 0.f);
            op[2 * j + 1] = fmaxf(mhi + bias[2 * j + 1], 0.f);
        }
    }
}

// ---------------------------------------------------------------------------
// conv2: P1(16,127,127,16)*W2(3,3,16,32) -> relu -> pool -> P2(16,62,62,32)
// ---------------------------------------------------------------------------
__global__ __launch_bounds__(512, 1) void conv2_kernel(
    const float* __restrict__ W, const float* __restrict__ bias)
{
    __shared__ __align__(16) float sW[3 * 3 * 16 * 32];
    __shared__ __align__(16) float sIn[4][34][35];

    const int b   = blockIdx.z;
    const int ph0 = blockIdx.y * 16, pw0 = blockIdx.x * 16;
    const int t   = threadIdx.x;
    const int coh = (t >> 8) * 16;
    const int pix = t & 255;
    const int py  = pix >> 4, px = pix & 15;

    for (int i = t; i < 4608; i += 512) sW[i] = W[i];

    unsigned long long acc[4][8];
#pragma unroll
    for (int k = 0; k < 4; ++k)
#pragma unroll
        for (int j = 0; j < 8; ++j) acc[k][j] = 0ULL;

    const int r0 = 2 * ph0, c0 = 2 * pw0;

    for (int cc = 0; cc < 4; ++cc) {
        __syncthreads();
        for (int i = t; i < 34 * 34; i += 512) {
            int r = i / 34, c = i - 34 * (i / 34);
            int gr = r0 + r, gc = c0 + c;
            float4 v = make_float4(0.f, 0.f, 0.f, 0.f);
            if (gr < 127 && gc < 127)
                v = *(const float4*)(g_P1 + (((size_t)(b * 127 + gr) * 127 + gc) * 16 + cc * 4));
            sIn[0][r][c] = v.x; sIn[1][r][c] = v.y;
            sIn[2][r][c] = v.z; sIn[3][r][c] = v.w;
        }
        __syncthreads();
#pragma unroll
        for (int ky = 0; ky < 3; ++ky)
#pragma unroll
            for (int kx = 0; kx < 3; ++kx)
#pragma unroll
                for (int ci = 0; ci < 4; ++ci) {
                    const ulonglong2* wp =
                        (const ulonglong2*)&sW[(((ky * 3 + kx) * 16) + (cc * 4 + ci)) * 32 + coh];
                    ulonglong2 q0 = wp[0], q1 = wp[1], q2 = wp[2], q3 = wp[3];
                    int rr = 2 * py + ky, cl = 2 * px + kx;
                    fma8p(acc[0], pack2(sIn[ci][rr][cl]),         q0, q1, q2, q3);
                    fma8p(acc[1], pack2(sIn[ci][rr][cl + 1]),     q0, q1, q2, q3);
                    fma8p(acc[2], pack2(sIn[ci][rr + 1][cl]),     q0, q1, q2, q3);
                    fma8p(acc[3], pack2(sIn[ci][rr + 1][cl + 1]), q0, q1, q2, q3);
                }
    }

    const int ph = ph0 + py, pw = pw0 + px;
    if (ph < 62 && pw < 62) {
        float* op = g_P2 + (((size_t)(b * 62 + ph) * 62 + pw) * 32 + coh);
#pragma unroll
        for (int j = 0; j < 8; ++j) {
            float2 a0 = unpack2(acc[0][j]), a1 = unpack2(acc[1][j]);
            float2 a2 = unpack2(acc[2][j]), a3 = unpack2(acc[3][j]);
            float mlo = fmaxf(fmaxf(a0.x, a1.x), fmaxf(a2.x, a3.x));
            float mhi = fmaxf(fmaxf(a0.y, a1.y), fmaxf(a2.y, a3.y));
            op[2 * j]     = fmaxf(mlo + bias[coh + 2 * j], 0.f);
            op[2 * j + 1] = fmaxf(mhi + bias[coh + 2 * j + 1], 0.f);
        }
    }
}

// ---------------------------------------------------------------------------
// conv3: P2(16,62,62,32)*W3(3,3,32,32) -> relu -> pool -> partial channel sums
// (global mean fused; P3 never materialized). Deterministic tree reduction.
// ---------------------------------------------------------------------------
__global__ __launch_bounds__(128, 2) void conv3_kernel(
    const float* __restrict__ W, const float* __restrict__ bias)
{
    __shared__ __align__(16) float sW[3 * 3 * 32 * 32];
    __shared__ __align__(16) float sIn[4][18][19];
    __shared__ float sRed[64][32];

    const int b   = blockIdx.z;
    const int ph0 = blockIdx.y * 8, pw0 = blockIdx.x * 8;
    const int t   = threadIdx.x;
    const int coh = (t >> 6) * 16;
    const int pix = t & 63;
    const int py  = pix >> 3, px = pix & 7;

    for (int i = t; i < 9216; i += 128) sW[i] = W[i];

    unsigned long long acc[4][8];
#pragma unroll
    for (int k = 0; k < 4; ++k)
#pragma unroll
        for (int j = 0; j < 8; ++j) acc[k][j] = 0ULL;

    const int r0 = 2 * ph0, c0 = 2 * pw0;

    for (int cc = 0; cc < 8; ++cc) {
        __syncthreads();
        for (int i = t; i < 18 * 18; i += 128) {
            int r = i / 18, c = i - 18 * (i / 18);
            int gr = r0 + r, gc = c0 + c;
            float4 v = make_float4(0.f, 0.f, 0.f, 0.f);
            if (gr < 62 && gc < 62)
                v = *(const float4*)(g_P2 + (((size_t)(b * 62 + gr) * 62 + gc) * 32 + cc * 4));
            sIn[0][r][c] = v.x; sIn[1][r][c] = v.y;
            sIn[2][r][c] = v.z; sIn[3][r][c] = v.w;
        }
        __syncthreads();
#pragma unroll
        for (int ky = 0; ky < 3; ++ky)
#pragma unroll
            for (int kx = 0; kx < 3; ++kx)
#pragma unroll
                for (int ci = 0; ci < 4; ++ci) {
                    const ulonglong2* wp =
                        (const ulonglong2*)&sW[(((ky * 3 + kx) * 32) + (cc * 4 + ci)) * 32 + coh];
                    ulonglong2 q0 = wp[0], q1 = wp[1], q2 = wp[2], q3 = wp[3];
                    int rr = 2 * py + ky, cl = 2 * px + kx;
                    fma8p(acc[0], pack2(sIn[ci][rr][cl]),         q0, q1, q2, q3);
                    fma8p(acc[1], pack2(sIn[ci][rr][cl + 1]),     q0, q1, q2, q3);
                    fma8p(acc[2], pack2(sIn[ci][rr + 1][cl]),     q0, q1, q2, q3);
                    fma8p(acc[3], pack2(sIn[ci][rr + 1][cl + 1]), q0, q1, q2, q3);
                }
    }

    const int ph = ph0 + py, pw = pw0 + px;
    const bool valid = (ph < 30) && (pw < 30);
#pragma unroll
    for (int j = 0; j < 8; ++j) {
        float2 a0 = unpack2(acc[0][j]), a1 = unpack2(acc[1][j]);
        float2 a2 = unpack2(acc[2][j]), a3 = unpack2(acc[3][j]);
        float mlo = fmaxf(fmaxf(a0.x, a1.x), fmaxf(a2.x, a3.x));
        float mhi = fmaxf(fmaxf(a0.y, a1.y), fmaxf(a2.y, a3.y));
        float vlo = fmaxf(mlo + bias[coh + 2 * j], 0.f);
        float vhi = fmaxf(mhi + bias[coh + 2 * j + 1], 0.f);
        sRed[pix][coh + 2 * j]     = valid ? vlo : 0.f;
        sRed[pix][coh + 2 * j + 1] = valid ? vhi : 0.f;
    }
    __syncthreads();

    if (t < 32) {
        float s = 0.f;
#pragma unroll
        for (int p = 0; p < 64; ++p) s += sRed[p][t];
        g_part[b][blockIdx.y * 4 + blockIdx.x][t] = s;
    }
}

// ---------------------------------------------------------------------------
// head: sum 16 tile partials -> mean -> dense 32->64 relu ->32 relu ->6
// ---------------------------------------------------------------------------
__global__ __launch_bounds__(64) void head_kernel(
    const float* __restrict__ D1, const float* __restrict__ db1,
    const float* __restrict__ D2, const float* __restrict__ db2,
    const float* __restrict__ D3, const float* __restrict__ db3)
{
    __shared__ float h0[32], h1[64], h2[32];
    const int b = blockIdx.x;
    const int t = threadIdx.x;

    if (t < 32) {
        float s = 0.f;
#pragma unroll
        for (int tile = 0; tile < 16; ++tile) s += g_part[b][tile][t];
        h0[t] = s * (1.f / 900.f);
    }
    __syncthreads();

    {
        float a = db1[t];
#pragma unroll
        for (int k = 0; k < 32; ++k) a = fmaf(h0[k], D1[k * 64 + t], a);
        h1[t] = fmaxf(a, 0.f);
    }
    __syncthreads();

    if (t < 32) {
        float a = db2[t];
#pragma unroll
        for (int k = 0; k < 64; ++k) a = fmaf(h1[k], D2[k * 32 + t], a);
        h2[t] = fmaxf(a, 0.f);
    }
    __syncthreads();

    if (t < 6) {
        float a = db3[t];
#pragma unroll
        for (int k = 0; k < 32; ++k) a = fmaf(h2[k], D3[k * 6 + t], a);
        g_theta[b * 6 + t] = a;
    }
}

// ---------------------------------------------------------------------------
// sampler: affine grid + bilinear sample of x(16,256,256,32).
// 256 threads = 64 pixels x 4 thread-groups of 8 channels.
// ---------------------------------------------------------------------------
__global__ __launch_bounds__(256) void sampler_kernel(
    const float* __restrict__ x, float* __restrict__ out)
{
    __shared__ float th[6];
    const int b = blockIdx.y;
    if (threadIdx.x < 6) th[threadIdx.x] = g_theta[b * 6 + threadIdx.x];
    __syncthreads();

    const int idx = blockIdx.x * 64 + (threadIdx.x >> 2);
    const int c8  = (threadIdx.x & 3) * 8;
    const int i   = idx >> 8;      // H index
    const int j   = idx & 255;     // W index

    const float xs = -1.f + (float)j * (2.f / 255.f);
    const float ys = -1.f + (float)i * (2.f / 255.f);

    const float xc = th[0] * xs + th[1] * ys + th[2];
    const float yc = th[3] * xs + th[4] * ys + th[5];

    const float xf = 0.5f * ((xc + 1.0f) * 254.0f);
    const float yf = 0.5f * ((yc + 1.0f) * 254.0f);

    int x0 = (int)floorf(xf); int x1 = x0 + 1;
    int y0 = (int)floorf(yf); int y1 = y0 + 1;
    x0 = min(max(x0, 0), 255); x1 = min(max(x1, 0), 255);
    y0 = min(max(y0, 0), 255); y1 = min(max(y1, 0), 255);

    const float x0f = (float)x0, x1f = (float)x1;
    const float y0f = (float)y0, y1f = (float)y1;

    const float wa = (x1f - xf) * (y1f - yf);
    const float wb = (x1f - xf) * (yf - y0f);
    const float wc = (xf - x0f) * (y1f - yf);
    const float wd = (xf - x0f) * (yf - y0f);

    const float* xb = x + (size_t)b * 256 * 256 * 32;
    const float* pa = xb + ((size_t)(y0 * 256 + x0) * 32 + c8);
    const float* pb = xb + ((size_t)(y1 * 256 + x0) * 32 + c8);
    const float* pc = xb + ((size_t)(y0 * 256 + x1) * 32 + c8);
    const float* pd = xb + ((size_t)(y1 * 256 + x1) * 32 + c8);
    float* po = out + ((size_t)(b * 65536 + idx) * 32 + c8);

#pragma unroll
    for (int h = 0; h < 2; ++h) {
        const float4 Ia = __ldg((const float4*)(pa + 4 * h));
        const float4 Ib = __ldg((const float4*)(pb + 4 * h));
        const float4 Ic = __ldg((const float4*)(pc + 4 * h));
        const float4 Id = __ldg((const float4*)(pd + 4 * h));
        float4 r;
        r.x = wa * Ia.x + wb * Ib.x + wc * Ic.x + wd * Id.x;
        r.y = wa * Ia.y + wb * Ib.y + wc * Ic.y + wd * Id.y;
        r.z = wa * Ia.z + wb * Ib.z + wc * Ic.z + wd * Id.z;
        r.w = wa * Ia.w + wb * Ib.w + wc * Ic.w + wd * Id.w;
        *(float4*)(po + 4 * h) = r;
    }
}

// ---------------------------------------------------------------------------
extern "C" void kernel_launch(void* const* d_in, const int* in_sizes, int n_in,
                              void* d_out, int out_size)
{
    const float* x   = (const float*)d_in[0];
    const float* W1  = (const float*)d_in[1];
    const float* b1  = (const float*)d_in[2];
    const float* W2  = (const float*)d_in[3];
    const float* b2  = (const float*)d_in[4];
    const float* W3  = (const float*)d_in[5];
    const float* b3  = (const float*)d_in[6];
    const float* D1  = (const float*)d_in[7];
    const float* db1 = (const float*)d_in[8];
    const float* D2  = (const float*)d_in[9];
    const float* db2 = (const float*)d_in[10];
    const float* D3  = (const float*)d_in[11];
    const float* db3 = (const float*)d_in[12];
    float* out = (float*)d_out;

    conv1_kernel<<<dim3(8, 8, 16), 256>>>(x, W1, b1);
    conv2_kernel<<<dim3(4, 4, 16), 512>>>(W2, b2);
    conv3_kernel<<<dim3(4, 4, 16), 128>>>(W3, b3);
    head_kernel<<<16, 64>>>(D1, db1, D2, db2, D3, db3);
    sampler_kernel<<<dim3(1024, 16), 256>>>(x, out);
}

// round 5
// speedup vs baseline: 1.0268x; 1.0268x over previous
#include <cuda_runtime.h>
#include <math.h>

// ---------------------------------------------------------------------------
// STN, fp32 throughout (theta errors amplify x127 into pixel shifts; tf32/bf16
// convs would blow the 1e-3 budget: measured amplification ~300x).
// R4: spill-free conv tiling (8 couts/thread, 64-reg accumulators),
//     input register cache reused across (ky,kx),
//     W1/W2 in __constant__ (LDCU->UR operand experiment to beat FFMA2 rt=3).
// ---------------------------------------------------------------------------

__device__ __align__(16) float g_P1[16 * 127 * 127 * 16];
__device__ __align__(16) float g_P2[16 * 62 * 62 * 32];
__device__ __align__(16) float g_part[16][8][32];   // [batch][tile][channel]
__device__ __align__(16) float g_theta[16 * 6];

__constant__ float c_W1[3 * 3 * 32 * 16];
__constant__ float c_b1[16];
__constant__ float c_W2[3 * 3 * 16 * 32];
__constant__ float c_b2[32];

// ---- packed f32x2 helpers (FFMA2: ptxas never emits; PTX-only) ------------
__device__ __forceinline__ unsigned long long pack2(float v) {
    unsigned long long r;
    asm("mov.b64 %0, {%1, %1};" : "=l"(r) : "r"(__float_as_uint(v)));
    return r;
}
__device__ __forceinline__ void ffma2(unsigned long long& a,
                                      unsigned long long v,
                                      unsigned long long w) {
    asm("fma.rn.f32x2 %0, %1, %2, %0;" : "+l"(a) : "l"(v), "l"(w));
}
__device__ __forceinline__ float2 unpack2(unsigned long long a) {
    float lo, hi;
    asm("mov.b64 {%0, %1}, %2;" : "=f"(lo), "=f"(hi) : "l"(a));
    return make_float2(lo, hi);
}

// ---------------------------------------------------------------------------
// conv1: x(16,256,256,32)*W1+b1 -> relu -> pool2 -> P1(16,127,127,16)
// Block 256 thr = 128 pixel-slots (16 rows x 8 col-pairs) x 2 cout-groups.
// Thread: conv 2x4 pixel block, 8 couts -> 32 u64 accs (64 regs, no spill).
// Weights from __constant__ (warp-uniform -> LDCU/UR candidates).
// ---------------------------------------------------------------------------
__global__ __launch_bounds__(256, 2) void conv1_kernel(const float* __restrict__ x)
{
    __shared__ __align__(16) float sIn[4][34][36];

    const int b  = blockIdx.z;
    const int by = blockIdx.y, bx = blockIdx.x;
    const int t  = threadIdx.x;
    const int grp  = t >> 7;        // 0..1 -> couts 8*grp
    const int slot = t & 127;
    const int py   = slot >> 3;     // 0..15
    const int pxi  = slot & 7;      // 0..7
    const int r0 = by * 32, c0 = bx * 32;

    unsigned long long acc[2][4][4];
#pragma unroll
    for (int dr = 0; dr < 2; ++dr)
#pragma unroll
        for (int dc = 0; dc < 4; ++dc)
#pragma unroll
            for (int j = 0; j < 4; ++j) acc[dr][dc][j] = 0ULL;

    for (int cc = 0; cc < 8; ++cc) {
        __syncthreads();
        for (int i = t; i < 34 * 34; i += 256) {
            int r = i / 34, c = i - 34 * (i / 34);
            int gr = r0 + r, gc = c0 + c;
            float4 v = make_float4(0.f, 0.f, 0.f, 0.f);
            if (gr < 256 && gc < 256)
                v = *(const float4*)(x + (((size_t)(b * 256 + gr) * 256 + gc) * 32 + cc * 4));
            sIn[0][r][c] = v.x; sIn[1][r][c] = v.y;
            sIn[2][r][c] = v.z; sIn[3][r][c] = v.w;
        }
        __syncthreads();

#pragma unroll
        for (int ci = 0; ci < 4; ++ci) {
            float v[4][6];
#pragma unroll
            for (int dr = 0; dr < 4; ++dr) {
                const float* row = &sIn[ci][2 * py + dr][4 * pxi];
                float4 f = *(const float4*)row;
                float2 g = *(const float2*)(row + 4);
                v[dr][0] = f.x; v[dr][1] = f.y; v[dr][2] = f.z;
                v[dr][3] = f.w; v[dr][4] = g.x; v[dr][5] = g.y;
            }
#pragma unroll
            for (int ky = 0; ky < 3; ++ky)
#pragma unroll
                for (int kx = 0; kx < 3; ++kx) {
                    const ulonglong2* wp = (const ulonglong2*)
                        &c_W1[(((ky * 3 + kx) * 32) + cc * 4 + ci) * 16 + 8 * grp];
                    ulonglong2 qa = wp[0], qb = wp[1];
#pragma unroll
                    for (int dr = 0; dr < 2; ++dr)
#pragma unroll
                        for (int dc = 0; dc < 4; ++dc) {
                            unsigned long long vv = pack2(v[ky + dr][kx + dc]);
                            ffma2(acc[dr][dc][0], vv, qa.x);
                            ffma2(acc[dr][dc][1], vv, qa.y);
                            ffma2(acc[dr][dc][2], vv, qb.x);
                            ffma2(acc[dr][dc][3], vv, qb.y);
                        }
                }
        }
    }

    const int ph = by * 16 + py;
#pragma unroll
    for (int s = 0; s < 2; ++s) {
        const int pw = bx * 16 + 2 * pxi + s;
        if (ph < 127 && pw < 127) {
            float* op = g_P1 + ((size_t)(b * 127 + ph) * 127 + pw) * 16 + 8 * grp;
#pragma unroll
            for (int j = 0; j < 4; ++j) {
                float2 a0 = unpack2(acc[0][2 * s][j]);
                float2 a1 = unpack2(acc[0][2 * s + 1][j]);
                float2 a2 = unpack2(acc[1][2 * s][j]);
                float2 a3 = unpack2(acc[1][2 * s + 1][j]);
                float mlo = fmaxf(fmaxf(a0.x, a1.x), fmaxf(a2.x, a3.x));
                float mhi = fmaxf(fmaxf(a0.y, a1.y), fmaxf(a2.y, a3.y));
                op[2 * j]     = fmaxf(mlo + c_b1[8 * grp + 2 * j], 0.f);
                op[2 * j + 1] = fmaxf(mhi + c_b1[8 * grp + 2 * j + 1], 0.f);
            }
        }
    }
}

// ---------------------------------------------------------------------------
// conv2: P1(16,127,127,16)*W2+b2 -> relu -> pool -> P2(16,62,62,32)
// Block 256 thr = 64 slots (8 rows x 8 col-pairs) x 4 cout-groups.
// ---------------------------------------------------------------------------
__global__ __launch_bounds__(256, 2) void conv2_kernel()
{
    __shared__ __align__(16) float sIn[4][18][36];

    const int b  = blockIdx.z;
    const int by = blockIdx.y, bx = blockIdx.x;
    const int t  = threadIdx.x;
    const int grp  = t >> 6;        // 0..3 -> couts 8*grp
    const int slot = t & 63;
    const int py   = slot >> 3;     // 0..7
    const int pxi  = slot & 7;      // 0..7
    const int r0 = by * 16, c0 = bx * 32;

    unsigned long long acc[2][4][4];
#pragma unroll
    for (int dr = 0; dr < 2; ++dr)
#pragma unroll
        for (int dc = 0; dc < 4; ++dc)
#pragma unroll
            for (int j = 0; j < 4; ++j) acc[dr][dc][j] = 0ULL;

    for (int cc = 0; cc < 4; ++cc) {
        __syncthreads();
        for (int i = t; i < 18 * 34; i += 256) {
            int r = i / 34, c = i - 34 * (i / 34);
            int gr = r0 + r, gc = c0 + c;
            float4 v = make_float4(0.f, 0.f, 0.f, 0.f);
            if (gr < 127 && gc < 127)
                v = *(const float4*)(g_P1 + (((size_t)(b * 127 + gr) * 127 + gc) * 16 + cc * 4));
            sIn[0][r][c] = v.x; sIn[1][r][c] = v.y;
            sIn[2][r][c] = v.z; sIn[3][r][c] = v.w;
        }
        __syncthreads();

#pragma unroll
        for (int ci = 0; ci < 4; ++ci) {
            float v[4][6];
#pragma unroll
            for (int dr = 0; dr < 4; ++dr) {
                const float* row = &sIn[ci][2 * py + dr][4 * pxi];
                float4 f = *(const float4*)row;
                float2 g = *(const float2*)(row + 4);
                v[dr][0] = f.x; v[dr][1] = f.y; v[dr][2] = f.z;
                v[dr][3] = f.w; v[dr][4] = g.x; v[dr][5] = g.y;
            }
#pragma unroll
            for (int ky = 0; ky < 3; ++ky)
#pragma unroll
                for (int kx = 0; kx < 3; ++kx) {
                    const ulonglong2* wp = (const ulonglong2*)
                        &c_W2[(((ky * 3 + kx) * 16) + cc * 4 + ci) * 32 + 8 * grp];
                    ulonglong2 qa = wp[0], qb = wp[1];
#pragma unroll
                    for (int dr = 0; dr < 2; ++dr)
#pragma unroll
                        for (int dc = 0; dc < 4; ++dc) {
                            unsigned long long vv = pack2(v[ky + dr][kx + dc]);
                            ffma2(acc[dr][dc][0], vv, qa.x);
                            ffma2(acc[dr][dc][1], vv, qa.y);
                            ffma2(acc[dr][dc][2], vv, qb.x);
                            ffma2(acc[dr][dc][3], vv, qb.y);
                        }
                }
        }
    }

    const int ph = by * 8 + py;
#pragma unroll
    for (int s = 0; s < 2; ++s) {
        const int pw = bx * 16 + 2 * pxi + s;
        if (ph < 62 && pw < 62) {
            float* op = g_P2 + ((size_t)(b * 62 + ph) * 62 + pw) * 32 + 8 * grp;
#pragma unroll
            for (int j = 0; j < 4; ++j) {
                float2 a0 = unpack2(acc[0][2 * s][j]);
                float2 a1 = unpack2(acc[0][2 * s + 1][j]);
                float2 a2 = unpack2(acc[1][2 * s][j]);
                float2 a3 = unpack2(acc[1][2 * s + 1][j]);
                float mlo = fmaxf(fmaxf(a0.x, a1.x), fmaxf(a2.x, a3.x));
                float mhi = fmaxf(fmaxf(a0.y, a1.y), fmaxf(a2.y, a3.y));
                op[2 * j]     = fmaxf(mlo + c_b2[8 * grp + 2 * j], 0.f);
                op[2 * j + 1] = fmaxf(mhi + c_b2[8 * grp + 2 * j + 1], 0.f);
            }
        }
    }
}

// ---------------------------------------------------------------------------
// conv3: P2(16,62,62,32)*W3+b3 -> relu -> pool -> per-tile channel sums
// (mean fused; P3 never materialized). Weights per-chunk in smem (control arm
// vs the constant-memory experiment in conv1/conv2).
// Block 256 thr = 64 slots x 4 cout-groups; tile = pooled 8x16.
// ---------------------------------------------------------------------------
__global__ __launch_bounds__(256, 2) void conv3_kernel(
    const float* __restrict__ W, const float* __restrict__ bias)
{
    __shared__ __align__(16) float sIn[4][18][36];
    __shared__ __align__(16) float sW[9 * 4 * 32];     // [kk][ci4][co32] slice
    __shared__ float sRed[64][32];

    const int b  = blockIdx.z;
    const int by = blockIdx.y, bx = blockIdx.x;
    const int t  = threadIdx.x;
    const int grp  = t >> 6;
    const int slot = t & 63;
    const int py   = slot >> 3;
    const int pxi  = slot & 7;
    const int r0 = by * 16, c0 = bx * 32;

    unsigned long long acc[2][4][4];
#pragma unroll
    for (int dr = 0; dr < 2; ++dr)
#pragma unroll
        for (int dc = 0; dc < 4; ++dc)
#pragma unroll
            for (int j = 0; j < 4; ++j) acc[dr][dc][j] = 0ULL;

    for (int cc = 0; cc < 8; ++cc) {
        __syncthreads();
        for (int i = t; i < 18 * 34; i += 256) {
            int r = i / 34, c = i - 34 * (i / 34);
            int gr = r0 + r, gc = c0 + c;
            float4 v = make_float4(0.f, 0.f, 0.f, 0.f);
            if (gr < 62 && gc < 62)
                v = *(const float4*)(g_P2 + (((size_t)(b * 62 + gr) * 62 + gc) * 32 + cc * 4));
            sIn[0][r][c] = v.x; sIn[1][r][c] = v.y;
            sIn[2][r][c] = v.z; sIn[3][r][c] = v.w;
        }
        // stage weight slice for this ci-chunk: [kk 0..8][ci 0..3][co 0..31]
        for (int i = t; i < 1152; i += 256) {
            int kk = i >> 7, rem = i & 127;
            int ci = rem >> 5, co = rem & 31;
            sW[i] = W[((kk * 32) + cc * 4 + ci) * 32 + co];
        }
        __syncthreads();

#pragma unroll
        for (int ci = 0; ci < 4; ++ci) {
            float v[4][6];
#pragma unroll
            for (int dr = 0; dr < 4; ++dr) {
                const float* row = &sIn[ci][2 * py + dr][4 * pxi];
                float4 f = *(const float4*)row;
                float2 g = *(const float2*)(row + 4);
                v[dr][0] = f.x; v[dr][1] = f.y; v[dr][2] = f.z;
                v[dr][3] = f.w; v[dr][4] = g.x; v[dr][5] = g.y;
            }
#pragma unroll
            for (int ky = 0; ky < 3; ++ky)
#pragma unroll
                for (int kx = 0; kx < 3; ++kx) {
                    const ulonglong2* wp = (const ulonglong2*)
                        &sW[((ky * 3 + kx) * 4 + ci) * 32 + 8 * grp];
                    ulonglong2 qa = wp[0], qb = wp[1];
#pragma unroll
                    for (int dr = 0; dr < 2; ++dr)
#pragma unroll
                        for (int dc = 0; dc < 4; ++dc) {
                            unsigned long long vv = pack2(v[ky + dr][kx + dc]);
                            ffma2(acc[dr][dc][0], vv, qa.x);
                            ffma2(acc[dr][dc][1], vv, qa.y);
                            ffma2(acc[dr][dc][2], vv, qb.x);
                            ffma2(acc[dr][dc][3], vv, qb.y);
                        }
                }
        }
    }

    // relu(max-pool + bias), masked, then per-tile channel partial sums
    const int ph = by * 8 + py;
    float csum[8];
#pragma unroll
    for (int j = 0; j < 8; ++j) csum[j] = 0.f;
#pragma unroll
    for (int s = 0; s < 2; ++s) {
        const int pw = bx * 16 + 2 * pxi + s;
        const bool valid = (ph < 30) && (pw < 30);
#pragma unroll
        for (int j = 0; j < 4; ++j) {
            float2 a0 = unpack2(acc[0][2 * s][j]);
            float2 a1 = unpack2(acc[0][2 * s + 1][j]);
            float2 a2 = unpack2(acc[1][2 * s][j]);
            float2 a3 = unpack2(acc[1][2 * s + 1][j]);
            float mlo = fmaxf(fmaxf(a0.x, a1.x), fmaxf(a2.x, a3.x));
            float mhi = fmaxf(fmaxf(a0.y, a1.y), fmaxf(a2.y, a3.y));
            float vlo = fmaxf(mlo + bias[8 * grp + 2 * j], 0.f);
            float vhi = fmaxf(mhi + bias[8 * grp + 2 * j + 1], 0.f);
            if (valid) { csum[2 * j] += vlo; csum[2 * j + 1] += vhi; }
        }
    }
    __syncthreads();
#pragma unroll
    for (int j = 0; j < 8; ++j) sRed[slot][8 * grp + j] = csum[j];
    __syncthreads();

    if (t < 32) {
        float s = 0.f;
#pragma unroll
        for (int p = 0; p < 64; ++p) s += sRed[p][t];
        g_part[b][by * 2 + bx][t] = s;
    }
}

// ---------------------------------------------------------------------------
// head: sum 8 tile partials -> mean -> dense 32->64 relu ->32 relu ->6
// ---------------------------------------------------------------------------
__global__ __launch_bounds__(64) void head_kernel(
    const float* __restrict__ D1, const float* __restrict__ db1,
    const float* __restrict__ D2, const float* __restrict__ db2,
    const float* __restrict__ D3, const float* __restrict__ db3)
{
    __shared__ float h0[32], h1[64], h2[32];
    const int b = blockIdx.x;
    const int t = threadIdx.x;

    if (t < 32) {
        float s = 0.f;
#pragma unroll
        for (int tile = 0; tile < 8; ++tile) s += g_part[b][tile][t];
        h0[t] = s * (1.f / 900.f);
    }
    __syncthreads();

    {
        float a = db1[t];
#pragma unroll
        for (int k = 0; k < 32; ++k) a = fmaf(h0[k], D1[k * 64 + t], a);
        h1[t] = fmaxf(a, 0.f);
    }
    __syncthreads();

    if (t < 32) {
        float a = db2[t];
#pragma unroll
        for (int k = 0; k < 64; ++k) a = fmaf(h1[k], D2[k * 32 + t], a);
        h2[t] = fmaxf(a, 0.f);
    }
    __syncthreads();

    if (t < 6) {
        float a = db3[t];
#pragma unroll
        for (int k = 0; k < 32; ++k) a = fmaf(h2[k], D3[k * 6 + t], a);
        g_theta[b * 6 + t] = a;
    }
}

// ---------------------------------------------------------------------------
// sampler: affine grid + bilinear sample of x(16,256,256,32).
// ---------------------------------------------------------------------------
__global__ __launch_bounds__(256) void sampler_kernel(
    const float* __restrict__ x, float* __restrict__ out)
{
    __shared__ float th[6];
    const int b = blockIdx.y;
    if (threadIdx.x < 6) th[threadIdx.x] = g_theta[b * 6 + threadIdx.x];
    __syncthreads();

    const int idx = blockIdx.x * 64 + (threadIdx.x >> 2);
    const int c8  = (threadIdx.x & 3) * 8;
    const int i   = idx >> 8;      // H index
    const int j   = idx & 255;     // W index

    const float xs = -1.f + (float)j * (2.f / 255.f);
    const float ys = -1.f + (float)i * (2.f / 255.f);

    const float xc = th[0] * xs + th[1] * ys + th[2];
    const float yc = th[3] * xs + th[4] * ys + th[5];

    const float xf = 0.5f * ((xc + 1.0f) * 254.0f);
    const float yf = 0.5f * ((yc + 1.0f) * 254.0f);

    int x0 = (int)floorf(xf); int x1 = x0 + 1;
    int y0 = (int)floorf(yf); int y1 = y0 + 1;
    x0 = min(max(x0, 0), 255); x1 = min(max(x1, 0), 255);
    y0 = min(max(y0, 0), 255); y1 = min(max(y1, 0), 255);

    const float x0f = (float)x0, x1f = (float)x1;
    const float y0f = (float)y0, y1f = (float)y1;

    const float wa = (x1f - xf) * (y1f - yf);
    const float wb = (x1f - xf) * (yf - y0f);
    const float wc = (xf - x0f) * (y1f - yf);
    const float wd = (xf - x0f) * (yf - y0f);

    const float* xb = x + (size_t)b * 256 * 256 * 32;
    const float* pa = xb + ((size_t)(y0 * 256 + x0) * 32 + c8);
    const float* pb = xb + ((size_t)(y1 * 256 + x0) * 32 + c8);
    const float* pc = xb + ((size_t)(y0 * 256 + x1) * 32 + c8);
    const float* pd = xb + ((size_t)(y1 * 256 + x1) * 32 + c8);
    float* po = out + ((size_t)(b * 65536 + idx) * 32 + c8);

#pragma unroll
    for (int h = 0; h < 2; ++h) {
        const float4 Ia = __ldg((const float4*)(pa + 4 * h));
        const float4 Ib = __ldg((const float4*)(pb + 4 * h));
        const float4 Ic = __ldg((const float4*)(pc + 4 * h));
        const float4 Id = __ldg((const float4*)(pd + 4 * h));
        float4 r;
        r.x = wa * Ia.x + wb * Ib.x + wc * Ic.x + wd * Id.x;
        r.y = wa * Ia.y + wb * Ib.y + wc * Ic.y + wd * Id.y;
        r.z = wa * Ia.z + wb * Ib.z + wc * Ic.z + wd * Id.z;
        r.w = wa * Ia.w + wb * Ib.w + wc * Ic.w + wd * Id.w;
        *(float4*)(po + 4 * h) = r;
    }
}

// ---------------------------------------------------------------------------
extern "C" void kernel_launch(void* const* d_in, const int* in_sizes, int n_in,
                              void* d_out, int out_size)
{
    const float* x   = (const float*)d_in[0];
    const float* W3  = (const float*)d_in[5];
    const float* b3  = (const float*)d_in[6];
    const float* D1  = (const float*)d_in[7];
    const float* db1 = (const float*)d_in[8];
    const float* D2  = (const float*)d_in[9];
    const float* db2 = (const float*)d_in[10];
    const float* D3  = (const float*)d_in[11];
    const float* db3 = (const float*)d_in[12];
    float* out = (float*)d_out;

    // device->constant copies (async D2D: graph-capturable, allocation-free)
    cudaMemcpyToSymbolAsync(c_W1, d_in[1], 4608 * sizeof(float), 0,
                            cudaMemcpyDeviceToDevice, 0);
    cudaMemcpyToSymbolAsync(c_b1, d_in[2], 16 * sizeof(float), 0,
                            cudaMemcpyDeviceToDevice, 0);
    cudaMemcpyToSymbolAsync(c_W2, d_in[3], 4608 * sizeof(float), 0,
                            cudaMemcpyDeviceToDevice, 0);
    cudaMemcpyToSymbolAsync(c_b2, d_in[4], 32 * sizeof(float), 0,
                            cudaMemcpyDeviceToDevice, 0);

    conv1_kernel<<<dim3(8, 8, 16), 256>>>(x);
    conv2_kernel<<<dim3(4, 8, 16), 256>>>();
    conv3_kernel<<<dim3(2, 4, 16), 256>>>(W3, b3);
    head_kernel<<<16, 64>>>(D1, db1, D2, db2, D3, db3);
    sampler_kernel<<<dim3(1024, 16), 256>>>(x, out);
}